// round 1
// baseline (speedup 1.0000x reference)
#include <cuda_runtime.h>

// ---------------------------------------------------------------------------
// Problem constants: B=2, N=512, D_IN=D_OUT=64, TEMP=100, POOL_K=0.5 -> kn=256
// ---------------------------------------------------------------------------
#define NB 2
#define NN 512
#define ND 64
#define KN 256
#define TEMP_INV (1.0f/100.0f)
#define BN_EPS 1e-5f
#define SELU_SCALE 1.0507009873554804934193349852946f
#define SELU_ALPHA 1.6732632423543772848170429916717f

// Scratch (allocation-free: __device__ globals)
__device__ float g_h[NB*NN*ND];    // pre-BN h
__device__ float g_hw[NB*NN*ND];   // selu(h_bn) * w
__device__ float g_w[NB*NN];       // pool gate per row
__device__ float g_mean[ND];
__device__ float g_rstd[ND];

__device__ __forceinline__ float tanh_approx(float x) {
    float r;
    asm("tanh.approx.f32 %0, %1;" : "=f"(r) : "f"(x));
    return r;
}

// ---------------------------------------------------------------------------
// Kernel A: one block per (b, i).
//   Z = X_b @ (diag(x_i) * W)          (512x64 @ 64x64 GEMM, chunked by 64 j)
//   score_j = sum_e aw_e * tanh(Z[j,e] + ab_e)
//   attn = softmax(score / TEMP) over j
//   agg = attn @ X_b
//   h_i = agg @ pw + pw_b + x_i @ pwo + pwo_b     -> g_h
// ---------------------------------------------------------------------------
__global__ __launch_bounds__(256) void kernelA(
    const float* __restrict__ x,     // (B,N,64)
    const float* __restrict__ apw,   // (64,64) att_proj_w  [d][e]
    const float* __restrict__ apb,   // (64)
    const float* __restrict__ awt,   // (64,1) att_weight
    const float* __restrict__ pw,    // (64,64) pw_att_w
    const float* __restrict__ pwb,   // (64)
    const float* __restrict__ pwo,   // (64,64) pwo_att_w
    const float* __restrict__ pwob)  // (64)
{
    __shared__ __align__(16) float Xs[64][68];   // j-chunk, [j][d], pad 68
    __shared__ __align__(16) float Wi[64*64];    // diag(x_i)*W, [d][e]
    __shared__ float spart[16][68];              // partial score sums [te][j]
    __shared__ float scr[NN];                    // scores -> attn
    __shared__ float red[256];
    __shared__ float aggp[256];
    __shared__ float agg_s[64];
    __shared__ float xi_s[64], ab_s[64], aw_s[64];

    const int t = threadIdx.x;
    const int i = blockIdx.x;
    const int b = blockIdx.y;
    const float* xb = x + b * NN * ND;

    if (t < 64) {
        xi_s[t] = xb[i * ND + t];
        ab_s[t] = apb[t];
        aw_s[t] = awt[t];
    }
    __syncthreads();

    // Wi[d][e] = x_i[d] * W[d][e]
    #pragma unroll
    for (int k = 0; k < 16; k++) {
        int idx = t + k * 256;
        Wi[idx] = xi_s[idx >> 6] * apw[idx];
    }
    // (barrier inside chunk loop covers Wi visibility before first GEMM read)

    const int te = t & 15;           // 16 e-groups of 4
    const int tj = t >> 4;           // 16 j-groups of 4
    const int e0 = te * 4;
    const int j0 = tj * 4;

    for (int jc = 0; jc < 8; jc++) {
        // load 64-row j chunk of X (coalesced float4), row-major [j][d]
        #pragma unroll
        for (int k = 0; k < 4; k++) {
            int v = t + k * 256;
            int j = v >> 4, d4 = v & 15;
            float4 f = *(const float4*)&xb[(jc * 64 + j) * ND + d4 * 4];
            *(float4*)&Xs[j][d4 * 4] = f;
        }
        __syncthreads();

        // register-tiled GEMM: 4j x 4e per thread
        float acc[4][4] = {};
        #pragma unroll 8
        for (int d = 0; d < 64; d++) {
            float4 bv = *(const float4*)&Wi[d * 64 + e0];
            #pragma unroll
            for (int jj = 0; jj < 4; jj++) {
                float a = Xs[j0 + jj][d];
                acc[jj][0] += a * bv.x;
                acc[jj][1] += a * bv.y;
                acc[jj][2] += a * bv.z;
                acc[jj][3] += a * bv.w;
            }
        }

        // partial score: sum over this thread's 4 e's
        #pragma unroll
        for (int jj = 0; jj < 4; jj++) {
            float p = 0.f;
            #pragma unroll
            for (int q = 0; q < 4; q++)
                p += aw_s[e0 + q] * tanh_approx(acc[jj][q] + ab_s[e0 + q]);
            spart[te][j0 + jj] = p;
        }
        __syncthreads();

        if (t < 64) {
            float s = 0.f;
            #pragma unroll
            for (int k = 0; k < 16; k++) s += spart[k][t];
            scr[jc * 64 + t] = s;
        }
        __syncthreads();
    }

    // softmax over j with temperature (max-subtracted, matches jax.nn.softmax)
    {
        float m = fmaxf(scr[t], scr[t + 256]);
        red[t] = m;
        __syncthreads();
        for (int s = 128; s > 0; s >>= 1) {
            if (t < s) red[t] = fmaxf(red[t], red[t + s]);
            __syncthreads();
        }
        float mx = red[0];
        __syncthreads();
        float ea = __expf((scr[t] - mx) * TEMP_INV);
        float eb = __expf((scr[t + 256] - mx) * TEMP_INV);
        red[t] = ea + eb;
        __syncthreads();
        for (int s = 128; s > 0; s >>= 1) {
            if (t < s) red[t] += red[t + s];
            __syncthreads();
        }
        float inv = 1.f / red[0];
        scr[t] = ea * inv;
        scr[t + 256] = eb * inv;
        __syncthreads();
    }

    // agg[d] = sum_j attn[j] * X_b[j][d]
    {
        int d = t & 63, part = t >> 6;
        float a = 0.f;
        const float* xp = xb + part * 128 * ND + d;
        #pragma unroll 4
        for (int jj = 0; jj < 128; jj++)
            a += scr[part * 128 + jj] * xp[jj * ND];
        aggp[part * 64 + d] = a;
        __syncthreads();
        if (t < 64)
            agg_s[t] = aggp[t] + aggp[64 + t] + aggp[128 + t] + aggp[192 + t];
        __syncthreads();
    }

    // h_i[e] = agg@pw + pw_b + x_i@pwo + pwo_b
    if (t < 64) {
        float hacc = pwb[t] + pwob[t];
        #pragma unroll 8
        for (int dd = 0; dd < 64; dd++)
            hacc += agg_s[dd] * pw[dd * 64 + t] + xi_s[dd] * pwo[dd * 64 + t];
        g_h[(b * NN + i) * ND + t] = hacc;
    }
}

// ---------------------------------------------------------------------------
// Kernel B: deterministic batch-norm stats over all B*N=1024 rows per feature.
// ---------------------------------------------------------------------------
__global__ __launch_bounds__(256) void kernelB() {
    __shared__ float s1[256], s2[256];
    int t = threadIdx.x;
    int e = t & 63, part = t >> 6;
    float sum = 0.f, sq = 0.f;
    #pragma unroll 4
    for (int r = part; r < NB * NN; r += 4) {
        float v = g_h[r * ND + e];
        sum += v;
        sq += v * v;
    }
    s1[t] = sum;
    s2[t] = sq;
    __syncthreads();
    if (t < 64) {
        float S = s1[t] + s1[64 + t] + s1[128 + t] + s1[192 + t];
        float Q = s2[t] + s2[64 + t] + s2[128 + t] + s2[192 + t];
        float mean = S * (1.f / (NB * NN));
        float var = fmaxf(Q * (1.f / (NB * NN)) - mean * mean, 0.f);
        g_mean[t] = mean;
        g_rstd[t] = rsqrtf(var + BN_EPS);
    }
}

// ---------------------------------------------------------------------------
// Kernel C1: BN + SELU + pool gate, store hw = selu_h * w and w.
// One block (64 threads) per row.
// ---------------------------------------------------------------------------
__global__ __launch_bounds__(64) void kernelC1(
    const float* __restrict__ bn_g, const float* __restrict__ bn_b,
    const float* __restrict__ pool_w, const float* __restrict__ pool_b)
{
    __shared__ float pr[2];
    int r = blockIdx.x;
    int e = threadIdx.x;
    float h = g_h[r * ND + e];
    float hn = (h - g_mean[e]) * g_rstd[e] * bn_g[e] + bn_b[e];
    float s = hn > 0.f ? SELU_SCALE * hn
                       : SELU_SCALE * SELU_ALPHA * (__expf(hn) - 1.f);
    float p = s * pool_w[e];
    #pragma unroll
    for (int o = 16; o > 0; o >>= 1) p += __shfl_down_sync(0xffffffffu, p, o);
    if ((e & 31) == 0) pr[e >> 5] = p;
    __syncthreads();
    float logit = pr[0] + pr[1] + pool_b[0];
    float w = 1.f / (1.f + __expf(-logit));
    g_hw[r * ND + e] = s * w;
    if (e == 0) g_w[r] = w;
}

// ---------------------------------------------------------------------------
// Kernel C2: per-batch bitonic sort of (w, idx), top_k tie rule
// (value descending, index ascending), gather top-256 rows of hw.
// ---------------------------------------------------------------------------
__global__ __launch_bounds__(512) void kernelC2(float* __restrict__ out) {
    __shared__ float sv[NN];
    __shared__ int si[NN];
    int t = threadIdx.x;
    int b = blockIdx.x;
    sv[t] = g_w[b * NN + t];
    si[t] = t;

    for (int k = 2; k <= NN; k <<= 1) {
        for (int j = k >> 1; j > 0; j >>= 1) {
            __syncthreads();
            int ixj = t ^ j;
            if (ixj > t) {
                float v1 = sv[t], v2 = sv[ixj];
                int i1 = si[t], i2 = si[ixj];
                // element@ixj should precede element@t under (w desc, idx asc)?
                bool before21 = (v2 > v1) || (v2 == v1 && i2 < i1);
                bool up = ((t & k) == 0);
                if (up ? before21 : !before21) {
                    sv[t] = v2; sv[ixj] = v1;
                    si[t] = i2; si[ixj] = i1;
                }
            }
        }
    }
    __syncthreads();

    // gather top 256 rows, 2 threads per row (32 floats each)
    int r = t >> 1, half = t & 1;
    int src = si[r];
    const float* sp = g_hw + (b * NN + src) * ND + half * 32;
    float* dst = out + (b * KN + r) * ND + half * 32;
    #pragma unroll
    for (int q = 0; q < 8; q++)
        *(float4*)&dst[q * 4] = *(const float4*)&sp[q * 4];
}

// ---------------------------------------------------------------------------
// Launch (graph-capturable: kernel launches only, default stream ordering)
// ---------------------------------------------------------------------------
extern "C" void kernel_launch(void* const* d_in, const int* in_sizes, int n_in,
                              void* d_out, int out_size)
{
    const float* x     = (const float*)d_in[0];
    const float* apw   = (const float*)d_in[1];
    const float* apb   = (const float*)d_in[2];
    const float* awt   = (const float*)d_in[3];
    const float* pw    = (const float*)d_in[4];
    const float* pwb   = (const float*)d_in[5];
    const float* pwo   = (const float*)d_in[6];
    const float* pwob  = (const float*)d_in[7];
    const float* bn_g  = (const float*)d_in[8];
    const float* bn_b  = (const float*)d_in[9];
    const float* poolw = (const float*)d_in[10];
    const float* poolb = (const float*)d_in[11];
    float* out = (float*)d_out;

    dim3 gA(NN, NB);
    kernelA<<<gA, 256>>>(x, apw, apb, awt, pw, pwb, pwo, pwob);
    kernelB<<<1, 256>>>();
    kernelC1<<<NB * NN, 64>>>(bn_g, bn_b, poolw, poolb);
    kernelC2<<<NB, 512>>>(out);
}